// round 5
// baseline (speedup 1.0000x reference)
#include <cuda_runtime.h>
#include <math.h>

#define NSEQ 2048
#define HDIM 1024
#define NHEAD 16
#define DH 64
#define S2 1024        // 2 * span
#define SPAN 512
#define INV_SCALE 0.0721687836487032f   // 1/sqrt(64*3)

// ---------------- scratch (device globals; no allocations allowed) ----------
__device__ float g_Q[NHEAD * NSEQ * DH];
__device__ float g_K[NHEAD * NSEQ * DH];
__device__ float g_V[NHEAD * NSEQ * DH];
__device__ float g_PosK[NHEAD * S2 * DH];
__device__ float g_PosQ[NHEAD * S2 * DH];
__device__ float g_c2p[(size_t)NHEAD * NSEQ * S2];   // 134 MB
__device__ float g_p2c[(size_t)NHEAD * NSEQ * S2];   // 134 MB

// ------------------------------- tf32 mma -----------------------------------
__device__ __forceinline__ unsigned f2tf(float x) {
    unsigned r;
    asm("cvt.rna.tf32.f32 %0, %1;" : "=r"(r) : "f"(x));
    return r;
}

__device__ __forceinline__ void mma_tf32(float (&d)[4],
                                         unsigned a0, unsigned a1, unsigned a2, unsigned a3,
                                         unsigned b0, unsigned b1) {
    asm volatile(
        "mma.sync.aligned.m16n8k8.row.col.f32.tf32.tf32.f32 "
        "{%0,%1,%2,%3}, {%4,%5,%6,%7}, {%8,%9}, {%0,%1,%2,%3};"
        : "+f"(d[0]), "+f"(d[1]), "+f"(d[2]), "+f"(d[3])
        : "r"(a0), "r"(a1), "r"(a2), "r"(a3), "r"(b0), "r"(b1));
}

// One BK=16 step. As layout [k][m] (ldsa), Bs layout [k][n] (ldsb), values
// already tf32-converted bit patterns stored as float.
template <int MT, int NT>
__device__ __forceinline__ void mma_bk16(const float* __restrict__ As, int ldsa,
                                         const float* __restrict__ Bs, int ldsb,
                                         int wm0, int wn0, int lane,
                                         float (&acc)[MT][NT][4]) {
    const int kq = lane & 3, rq = lane >> 2;
#pragma unroll
    for (int s = 0; s < 2; s++) {
        const int k0 = s * 8 + kq;
        unsigned a[MT][4];
#pragma unroll
        for (int mt = 0; mt < MT; mt++) {
            const int m = wm0 + mt * 16 + rq;
            a[mt][0] = __float_as_uint(As[k0 * ldsa + m]);
            a[mt][1] = __float_as_uint(As[k0 * ldsa + m + 8]);
            a[mt][2] = __float_as_uint(As[(k0 + 4) * ldsa + m]);
            a[mt][3] = __float_as_uint(As[(k0 + 4) * ldsa + m + 8]);
        }
#pragma unroll
        for (int nt = 0; nt < NT; nt++) {
            const int n = wn0 + nt * 8 + rq;
            unsigned b0 = __float_as_uint(Bs[k0 * ldsb + n]);
            unsigned b1 = __float_as_uint(Bs[(k0 + 4) * ldsb + n]);
#pragma unroll
            for (int mt = 0; mt < MT; mt++)
                mma_tf32(acc[mt][nt], a[mt][0], a[mt][1], a[mt][2], a[mt][3], b0, b1);
        }
    }
}

// ---------------------------------------------------------------------------
// K1: QKV projection. M=2048, N=3072, K=1024. BM=BN=128, BK=16, double-buffered.
// ---------------------------------------------------------------------------
__global__ void __launch_bounds__(256) qkv_kernel(const float* __restrict__ hidden,
                                                  const float* __restrict__ W,
                                                  const float* __restrict__ qb,
                                                  const float* __restrict__ vb) {
    __shared__ float As[2][16 * 132];
    __shared__ float Bs[2][16 * 132];
    const int t = threadIdx.x, lane = t & 31, wid = t >> 5;
    const int wm0 = (wid >> 1) * 32, wn0 = (wid & 1) * 64;
    const int m0 = blockIdx.y * 128, n0 = blockIdx.x * 128;
    const int r0 = t >> 2, g = t & 3;

    float acc[2][8][4];
#pragma unroll
    for (int mt = 0; mt < 2; mt++)
#pragma unroll
        for (int nt = 0; nt < 8; nt++)
#pragma unroll
            for (int e = 0; e < 4; e++) acc[mt][nt][e] = 0.0f;

    float4 ra[2], rb[2];
    auto ldg = [&](int kt) {
        ra[0] = *(const float4*)&hidden[(size_t)(m0 + r0) * HDIM + kt + g * 4];
        ra[1] = *(const float4*)&hidden[(size_t)(m0 + r0 + 64) * HDIM + kt + g * 4];
        rb[0] = *(const float4*)&W[(size_t)(n0 + r0) * HDIM + kt + g * 4];
        rb[1] = *(const float4*)&W[(size_t)(n0 + r0 + 64) * HDIM + kt + g * 4];
    };
    auto sts = [&](int buf) {
        const float* pa = (const float*)ra;
        const float* pb = (const float*)rb;
#pragma unroll
        for (int half = 0; half < 2; half++) {
            int r = r0 + half * 64;
#pragma unroll
            for (int e = 0; e < 4; e++) {
                As[buf][(g * 4 + e) * 132 + r] = __uint_as_float(f2tf(pa[half * 4 + e]));
                Bs[buf][(g * 4 + e) * 132 + r] = __uint_as_float(f2tf(pb[half * 4 + e]));
            }
        }
    };

    ldg(0); sts(0);
    const int nt_tiles = HDIM / 16;
    for (int kt = 0; kt < nt_tiles; kt++) {
        __syncthreads();
        if (kt + 1 < nt_tiles) ldg((kt + 1) * 16);
        mma_bk16<2, 8>(As[kt & 1], 132, Bs[kt & 1], 132, wm0, wn0, lane, acc);
        if (kt + 1 < nt_tiles) sts((kt + 1) & 1);
    }

    const int kq = lane & 3, rq = lane >> 2;
#pragma unroll
    for (int mt = 0; mt < 2; mt++)
#pragma unroll
        for (int nt = 0; nt < 8; nt++)
#pragma unroll
            for (int h2 = 0; h2 < 2; h2++) {
                int m  = m0 + wm0 + mt * 16 + rq + h2 * 8;
                int cg = n0 + wn0 + nt * 8 + kq * 2;
                int head = cg / 192;
                int jj = cg - head * 192;
                float v0 = acc[mt][nt][h2 * 2], v1 = acc[mt][nt][h2 * 2 + 1];
                if (jj < 64) {
                    v0 = (v0 + qb[head * 64 + jj]) * INV_SCALE;
                    v1 = (v1 + qb[head * 64 + jj + 1]) * INV_SCALE;
                    *(float2*)&g_Q[(size_t)(head * NSEQ + m) * DH + jj] = make_float2(v0, v1);
                } else if (jj < 128) {
                    *(float2*)&g_K[(size_t)(head * NSEQ + m) * DH + jj - 64] = make_float2(v0, v1);
                } else {
                    v0 += vb[head * 64 + jj - 128];
                    v1 += vb[head * 64 + jj - 127];
                    *(float2*)&g_V[(size_t)(head * NSEQ + m) * DH + jj - 128] = make_float2(v0, v1);
                }
            }
}

// ---------------------------------------------------------------------------
// K2: position projections. z=0: PosK, z=1: PosQ. M=N=K=1024.
// ---------------------------------------------------------------------------
__global__ void __launch_bounds__(256) pos_kernel(const float* __restrict__ rel,
                                                  const float* __restrict__ Wk,
                                                  const float* __restrict__ Wq,
                                                  const float* __restrict__ bias) {
    __shared__ float As[2][16 * 132];
    __shared__ float Bs[2][16 * 132];
    const int which = blockIdx.z;
    const float* W = which == 0 ? Wk : Wq;
    const int t = threadIdx.x, lane = t & 31, wid = t >> 5;
    const int wm0 = (wid >> 1) * 32, wn0 = (wid & 1) * 64;
    const int m0 = blockIdx.y * 128, n0 = blockIdx.x * 128;
    const int r0 = t >> 2, g = t & 3;

    float acc[2][8][4];
#pragma unroll
    for (int mt = 0; mt < 2; mt++)
#pragma unroll
        for (int nt = 0; nt < 8; nt++)
#pragma unroll
            for (int e = 0; e < 4; e++) acc[mt][nt][e] = 0.0f;

    float4 ra[2], rb[2];
    auto ldg = [&](int kt) {
        ra[0] = *(const float4*)&rel[(size_t)(m0 + r0) * HDIM + kt + g * 4];
        ra[1] = *(const float4*)&rel[(size_t)(m0 + r0 + 64) * HDIM + kt + g * 4];
        rb[0] = *(const float4*)&W[(size_t)(n0 + r0) * HDIM + kt + g * 4];
        rb[1] = *(const float4*)&W[(size_t)(n0 + r0 + 64) * HDIM + kt + g * 4];
    };
    auto sts = [&](int buf) {
        const float* pa = (const float*)ra;
        const float* pb = (const float*)rb;
#pragma unroll
        for (int half = 0; half < 2; half++) {
            int r = r0 + half * 64;
#pragma unroll
            for (int e = 0; e < 4; e++) {
                As[buf][(g * 4 + e) * 132 + r] = __uint_as_float(f2tf(pa[half * 4 + e]));
                Bs[buf][(g * 4 + e) * 132 + r] = __uint_as_float(f2tf(pb[half * 4 + e]));
            }
        }
    };

    ldg(0); sts(0);
    const int nt_tiles = HDIM / 16;
    for (int kt = 0; kt < nt_tiles; kt++) {
        __syncthreads();
        if (kt + 1 < nt_tiles) ldg((kt + 1) * 16);
        mma_bk16<2, 8>(As[kt & 1], 132, Bs[kt & 1], 132, wm0, wn0, lane, acc);
        if (kt + 1 < nt_tiles) sts((kt + 1) & 1);
    }

    const int kq = lane & 3, rq = lane >> 2;
#pragma unroll
    for (int mt = 0; mt < 2; mt++)
#pragma unroll
        for (int nt = 0; nt < 8; nt++)
#pragma unroll
            for (int h2 = 0; h2 < 2; h2++) {
                int s  = m0 + wm0 + mt * 16 + rq + h2 * 8;
                int cc = n0 + wn0 + nt * 8 + kq * 2;
                int head = cc >> 6, d = cc & 63;
                float v0 = acc[mt][nt][h2 * 2], v1 = acc[mt][nt][h2 * 2 + 1];
                if (which == 0) {
                    *(float2*)&g_PosK[(size_t)(head * S2 + s) * DH + d] = make_float2(v0, v1);
                } else {
                    v0 = (v0 + bias[cc]) * INV_SCALE;
                    v1 = (v1 + bias[cc + 1]) * INV_SCALE;
                    *(float2*)&g_PosQ[(size_t)(head * S2 + s) * DH + d] = make_float2(v0, v1);
                }
            }
}

// ---------------------------------------------------------------------------
// Shared fill for K=64 tiles: [128 rows x 64 k] -> T[k][m] (pad 132), tf32.
// ---------------------------------------------------------------------------
__device__ __forceinline__ void fill_k64(const float* __restrict__ src, int row0,
                                         float* __restrict__ Ts, int t) {
#pragma unroll
    for (int i = 0; i < 8; i++) {
        int lin4 = i * 256 + t;           // 2048 float4s
        int r = lin4 >> 4, g = lin4 & 15;
        float4 v = *(const float4*)&src[(size_t)(row0 + r) * DH + g * 4];
        Ts[(g * 4 + 0) * 132 + r] = __uint_as_float(f2tf(v.x));
        Ts[(g * 4 + 1) * 132 + r] = __uint_as_float(f2tf(v.y));
        Ts[(g * 4 + 2) * 132 + r] = __uint_as_float(f2tf(v.z));
        Ts[(g * 4 + 3) * 132 + r] = __uint_as_float(f2tf(v.w));
    }
}

// ---------------------------------------------------------------------------
// K3: raw relative scores. z = h + 16*which. K=64 single-shot.
// ---------------------------------------------------------------------------
__global__ void __launch_bounds__(256) relsc_kernel() {
    extern __shared__ float sm[];
    float* As = sm;
    float* Bs = sm + 64 * 132;
    const int z = blockIdx.z;
    const int h = z & 15, which = z >> 4;
    const int m0 = blockIdx.y * 128, n0 = blockIdx.x * 128;
    const float* A = (which == 0 ? g_Q : g_K) + (size_t)h * NSEQ * DH;
    const float* B = (which == 0 ? g_PosK : g_PosQ) + (size_t)h * S2 * DH;
    float* O = (which == 0 ? g_c2p : g_p2c);

    const int t = threadIdx.x, lane = t & 31, wid = t >> 5;
    const int wm0 = (wid >> 1) * 32, wn0 = (wid & 1) * 64;

    fill_k64(A, m0, As, t);
    fill_k64(B, n0, Bs, t);
    __syncthreads();

    float acc[2][8][4];
#pragma unroll
    for (int mt = 0; mt < 2; mt++)
#pragma unroll
        for (int nt = 0; nt < 8; nt++)
#pragma unroll
            for (int e = 0; e < 4; e++) acc[mt][nt][e] = 0.0f;

#pragma unroll
    for (int s16 = 0; s16 < 4; s16++)
        mma_bk16<2, 8>(As + s16 * 16 * 132, 132, Bs + s16 * 16 * 132, 132,
                       wm0, wn0, lane, acc);

    const int kq = lane & 3, rq = lane >> 2;
#pragma unroll
    for (int mt = 0; mt < 2; mt++)
#pragma unroll
        for (int nt = 0; nt < 8; nt++)
#pragma unroll
            for (int h2 = 0; h2 < 2; h2++) {
                int m = m0 + wm0 + mt * 16 + rq + h2 * 8;
                int n = n0 + wn0 + nt * 8 + kq * 2;
                *(float2*)&O[((size_t)(h * NSEQ + m)) * S2 + n] =
                    make_float2(acc[mt][nt][h2 * 2], acc[mt][nt][h2 * 2 + 1]);
            }
}

// ---------------------------------------------------------------------------
// K4: fused flash attention with tf32 MMA.
// Block = (head, q-tile of 128). 256 threads, 8 warps (16 q-rows each).
// smem: Qs[64][132] | Ks[64][132] | Vs[128][68] | G[128][132]
//   G reused: (c2p + p2c) bias tile -> P (tf32) for the PV MMA.
// ---------------------------------------------------------------------------
#define FL_QS 0
#define FL_KS (64 * 132)
#define FL_VS (FL_KS + 64 * 132)
#define FL_G  (FL_VS + 128 * 68)
#define FLASH_SMEM ((FL_G + 128 * 132) * 4)

__global__ void __launch_bounds__(256, 1) flash_kernel(const int* __restrict__ mask,
                                                       float* __restrict__ out) {
    extern __shared__ float sm[];
    float* Qs = sm + FL_QS;
    float* Ks = sm + FL_KS;
    float* Vs = sm + FL_VS;
    float* G  = sm + FL_G;

    const int h  = blockIdx.y;
    const int q0 = blockIdx.x * 128;
    const int t = threadIdx.x, lane = t & 31, wid = t >> 5;
    const int kq = lane & 3, rq = lane >> 2;
    const int wm0 = wid * 16;

    const float* Kg = g_K + (size_t)h * NSEQ * DH;
    const float* Vg = g_V + (size_t)h * NSEQ * DH;
    const float* C2 = g_c2p + (size_t)h * NSEQ * S2;
    const float* P2 = g_p2c + (size_t)h * NSEQ * S2;

    fill_k64(g_Q + (size_t)h * NSEQ * DH, q0, Qs, t);

    float m_i[2] = {-INFINITY, -INFINITY};
    float l_i[2] = {0.0f, 0.0f};
    float accO[1][8][4];
#pragma unroll
    for (int nt = 0; nt < 8; nt++)
#pragma unroll
        for (int e = 0; e < 4; e++) accO[0][nt][e] = 0.0f;

    for (int kt = 0; kt < NSEQ / 128; kt++) {
        const int k0 = kt * 128;
        __syncthreads();   // prev PV (reads G, Vs) done; Ks free

        // stage K[k][m=n-local], V[k][d], c2p tile into G[q-local][k-local]
        fill_k64(Kg, k0, Ks, t);
#pragma unroll
        for (int i = 0; i < 8; i++) {
            int lin4 = i * 256 + t;
            int r = lin4 >> 4, g = lin4 & 15;
            float4 v = *(const float4*)&Vg[(size_t)(k0 + r) * DH + g * 4];
            Vs[r * 68 + g * 4 + 0] = __uint_as_float(f2tf(v.x));
            Vs[r * 68 + g * 4 + 1] = __uint_as_float(f2tf(v.y));
            Vs[r * 68 + g * 4 + 2] = __uint_as_float(f2tf(v.z));
            Vs[r * 68 + g * 4 + 3] = __uint_as_float(f2tf(v.w));
        }
#pragma unroll
        for (int i = 0; i < 64; i++) {
            int lin = i * 256 + t;
            int r = lin >> 7, j = lin & 127;
            int q = q0 + r, kc = k0 + j;
            int idx = q - kc + SPAN;
            idx = idx < 0 ? 0 : (idx > S2 - 1 ? S2 - 1 : idx);
            G[r * 132 + j] = C2[(size_t)q * S2 + idx];
        }
        __syncthreads();

        // S = Q K^T
        float sacc[1][16][4];
#pragma unroll
        for (int nt = 0; nt < 16; nt++)
#pragma unroll
            for (int e = 0; e < 4; e++) sacc[0][nt][e] = 0.0f;
#pragma unroll
        for (int s16 = 0; s16 < 4; s16++)
            mma_bk16<1, 16>(Qs + s16 * 16 * 132, 132, Ks + s16 * 16 * 132, 132,
                            wm0, 0, lane, sacc);

        // add p2c into G (transposed fill, coalesced along q in global)
#pragma unroll
        for (int i = 0; i < 64; i++) {
            int lin = i * 256 + t;
            int jr = lin >> 7, qi = lin & 127;
            int kc = k0 + jr, q = q0 + qi;
            int idx = q - kc + SPAN;
            idx = idx < 0 ? 0 : (idx > S2 - 1 ? S2 - 1 : idx);
            G[qi * 132 + jr] += P2[(size_t)kc * S2 + idx];
        }
        __syncthreads();

        // S += bias, mask
        const int r0 = wm0 + rq, r1 = wm0 + rq + 8;
#pragma unroll
        for (int nt = 0; nt < 16; nt++) {
            int c = nt * 8 + kq * 2;
            float2 b0 = *(const float2*)&G[r0 * 132 + c];
            float2 b1 = *(const float2*)&G[r1 * 132 + c];
            int2 mk0 = *(const int2*)&mask[(size_t)(q0 + r0) * NSEQ + k0 + c];
            int2 mk1 = *(const int2*)&mask[(size_t)(q0 + r1) * NSEQ + k0 + c];
            sacc[0][nt][0] += b0.x; sacc[0][nt][1] += b0.y;
            sacc[0][nt][2] += b1.x; sacc[0][nt][3] += b1.y;
            if (mk0.x == 0) sacc[0][nt][0] = -1e30f;
            if (mk0.y == 0) sacc[0][nt][1] = -1e30f;
            if (mk1.x == 0) sacc[0][nt][2] = -1e30f;
            if (mk1.y == 0) sacc[0][nt][3] = -1e30f;
        }

        // online softmax: rows r0, r1 fully within lane quad
        float tmax0 = -INFINITY, tmax1 = -INFINITY;
#pragma unroll
        for (int nt = 0; nt < 16; nt++) {
            tmax0 = fmaxf(tmax0, fmaxf(sacc[0][nt][0], sacc[0][nt][1]));
            tmax1 = fmaxf(tmax1, fmaxf(sacc[0][nt][2], sacc[0][nt][3]));
        }
        tmax0 = fmaxf(tmax0, __shfl_xor_sync(0xffffffffu, tmax0, 1));
        tmax0 = fmaxf(tmax0, __shfl_xor_sync(0xffffffffu, tmax0, 2));
        tmax1 = fmaxf(tmax1, __shfl_xor_sync(0xffffffffu, tmax1, 1));
        tmax1 = fmaxf(tmax1, __shfl_xor_sync(0xffffffffu, tmax1, 2));

        float mn0 = fmaxf(m_i[0], tmax0), mn1 = fmaxf(m_i[1], tmax1);
        float es0 = __expf(m_i[0] - mn0), es1 = __expf(m_i[1] - mn1);
        m_i[0] = mn0; m_i[1] = mn1;

        float sum0 = 0.0f, sum1 = 0.0f;
#pragma unroll
        for (int nt = 0; nt < 16; nt++) {
            sacc[0][nt][0] = __expf(sacc[0][nt][0] - mn0);
            sacc[0][nt][1] = __expf(sacc[0][nt][1] - mn0);
            sacc[0][nt][2] = __expf(sacc[0][nt][2] - mn1);
            sacc[0][nt][3] = __expf(sacc[0][nt][3] - mn1);
            sum0 += sacc[0][nt][0] + sacc[0][nt][1];
            sum1 += sacc[0][nt][2] + sacc[0][nt][3];
        }
        sum0 += __shfl_xor_sync(0xffffffffu, sum0, 1);
        sum0 += __shfl_xor_sync(0xffffffffu, sum0, 2);
        sum1 += __shfl_xor_sync(0xffffffffu, sum1, 1);
        sum1 += __shfl_xor_sync(0xffffffffu, sum1, 2);
        l_i[0] = l_i[0] * es0 + sum0;
        l_i[1] = l_i[1] * es1 + sum1;
#pragma unroll
        for (int nt = 0; nt < 8; nt++) {
            accO[0][nt][0] *= es0; accO[0][nt][1] *= es0;
            accO[0][nt][2] *= es1; accO[0][nt][3] *= es1;
        }

        __syncthreads();   // all lanes done reading G
        // write P (tf32) into G as [k][m]
#pragma unroll
        for (int nt = 0; nt < 16; nt++) {
            int c = nt * 8 + kq * 2;
            G[(c + 0) * 132 + r0] = __uint_as_float(f2tf(sacc[0][nt][0]));
            G[(c + 1) * 132 + r0] = __uint_as_float(f2tf(sacc[0][nt][1]));
            G[(c + 0) * 132 + r1] = __uint_as_float(f2tf(sacc[0][nt][2]));
            G[(c + 1) * 132 + r1] = __uint_as_float(f2tf(sacc[0][nt][3]));
        }
        __syncthreads();

        // O += P V
#pragma unroll
        for (int s16 = 0; s16 < 8; s16++)
            mma_bk16<1, 8>(G + s16 * 16 * 132, 132, Vs + s16 * 16 * 68, 68,
                           wm0, 0, lane, accO);
    }

    // epilogue: normalize + write out[q][h*64 + d]
    const int r0 = wm0 + rq, r1 = wm0 + rq + 8;
    float inv0 = 1.0f / l_i[0], inv1 = 1.0f / l_i[1];
#pragma unroll
    for (int nt = 0; nt < 8; nt++) {
        int c = nt * 8 + kq * 2;
        *(float2*)&out[(size_t)(q0 + r0) * HDIM + h * DH + c] =
            make_float2(accO[0][nt][0] * inv0, accO[0][nt][1] * inv0);
        *(float2*)&out[(size_t)(q0 + r1) * HDIM + h * DH + c] =
            make_float2(accO[0][nt][2] * inv1, accO[0][nt][3] * inv1);
    }
}

// ---------------------------------------------------------------------------
extern "C" void kernel_launch(void* const* d_in, const int* in_sizes, int n_in,
                              void* d_out, int out_size) {
    const float* hidden   = (const float*)d_in[0];
    const int*   mask     = (const int*)  d_in[1];
    const float* rel_emb  = (const float*)d_in[3];
    const float* in_proj  = (const float*)d_in[4];
    const float* q_bias   = (const float*)d_in[5];
    const float* v_bias   = (const float*)d_in[6];
    const float* pos_w    = (const float*)d_in[7];
    const float* pos_q_w  = (const float*)d_in[8];
    const float* pos_q_b  = (const float*)d_in[9];
    float* out = (float*)d_out;

    const int relsc_smem = 2 * 64 * 132 * 4;
    cudaFuncSetAttribute(relsc_kernel, cudaFuncAttributeMaxDynamicSharedMemorySize,
                         relsc_smem);
    cudaFuncSetAttribute(flash_kernel, cudaFuncAttributeMaxDynamicSharedMemorySize,
                         FLASH_SMEM);

    // K1: QKV projection
    qkv_kernel<<<dim3(3072 / 128, 2048 / 128), 256>>>(hidden, in_proj, q_bias, v_bias);

    // K2: position projections
    pos_kernel<<<dim3(HDIM / 128, S2 / 128, 2), 256>>>(rel_emb, pos_w, pos_q_w, pos_q_b);

    // K3: c2p_raw / p2c_raw
    relsc_kernel<<<dim3(S2 / 128, NSEQ / 128, NHEAD * 2), 256, relsc_smem>>>();

    // K4: fused flash attention
    flash_kernel<<<dim3(NSEQ / 128, NHEAD), 256, FLASH_SMEM>>>(mask, out);
}

// round 6
// speedup vs baseline: 1.2294x; 1.2294x over previous
#include <cuda_runtime.h>
#include <math.h>

#define NSEQ 2048
#define HDIM 1024
#define NHEAD 16
#define DH 64
#define S2 1024        // 2 * span
#define SPAN 512
#define INV_SCALE 0.0721687836487032f   // 1/sqrt(64*3)

// ---------------- scratch (device globals; no allocations allowed) ----------
__device__ float g_Q[NHEAD * NSEQ * DH];
__device__ float g_K[NHEAD * NSEQ * DH];
__device__ float g_V[NHEAD * NSEQ * DH];
__device__ float g_PosK[NHEAD * S2 * DH];
__device__ float g_PosQ[NHEAD * S2 * DH];
__device__ float g_c2p[(size_t)NHEAD * NSEQ * S2];   // 134 MB
__device__ float g_p2c[(size_t)NHEAD * NSEQ * S2];   // 134 MB
__device__ float g_sc [(size_t)NHEAD * NSEQ * NSEQ]; // 268 MB raw masked scores
__device__ float g_statM[(size_t)NHEAD * NSEQ * 32]; // per-row per-halftile max
__device__ float g_statL[(size_t)NHEAD * NSEQ * 32]; // per-row per-halftile sumexp
__device__ float g_rowM  [NHEAD * NSEQ];
__device__ float g_rowInv[NHEAD * NSEQ];
__device__ float g_pvp[(size_t)4 * NHEAD * NSEQ * DH]; // split-K partials

// ------------------------------- tf32 mma -----------------------------------
__device__ __forceinline__ unsigned f2tf(float x) {
    unsigned r;
    asm("cvt.rna.tf32.f32 %0, %1;" : "=r"(r) : "f"(x));
    return r;
}

__device__ __forceinline__ void mma_tf32(float (&d)[4],
                                         unsigned a0, unsigned a1, unsigned a2, unsigned a3,
                                         unsigned b0, unsigned b1) {
    asm volatile(
        "mma.sync.aligned.m16n8k8.row.col.f32.tf32.tf32.f32 "
        "{%0,%1,%2,%3}, {%4,%5,%6,%7}, {%8,%9}, {%0,%1,%2,%3};"
        : "+f"(d[0]), "+f"(d[1]), "+f"(d[2]), "+f"(d[3])
        : "r"(a0), "r"(a1), "r"(a2), "r"(a3), "r"(b0), "r"(b1));
}

// One BK=16 step. As layout [k][m] (ldsa), Bs layout [k][n] (ldsb), values
// already tf32-converted bit patterns stored as float.
template <int MT, int NT>
__device__ __forceinline__ void mma_bk16(const float* __restrict__ As, int ldsa,
                                         const float* __restrict__ Bs, int ldsb,
                                         int wm0, int wn0, int lane,
                                         float (&acc)[MT][NT][4]) {
    const int kq = lane & 3, rq = lane >> 2;
#pragma unroll
    for (int s = 0; s < 2; s++) {
        const int k0 = s * 8 + kq;
        unsigned a[MT][4];
#pragma unroll
        for (int mt = 0; mt < MT; mt++) {
            const int m = wm0 + mt * 16 + rq;
            a[mt][0] = __float_as_uint(As[k0 * ldsa + m]);
            a[mt][1] = __float_as_uint(As[k0 * ldsa + m + 8]);
            a[mt][2] = __float_as_uint(As[(k0 + 4) * ldsa + m]);
            a[mt][3] = __float_as_uint(As[(k0 + 4) * ldsa + m + 8]);
        }
#pragma unroll
        for (int nt = 0; nt < NT; nt++) {
            const int n = wn0 + nt * 8 + rq;
            unsigned b0 = __float_as_uint(Bs[k0 * ldsb + n]);
            unsigned b1 = __float_as_uint(Bs[(k0 + 4) * ldsb + n]);
#pragma unroll
            for (int mt = 0; mt < MT; mt++)
                mma_tf32(acc[mt][nt], a[mt][0], a[mt][1], a[mt][2], a[mt][3], b0, b1);
        }
    }
}

// ---------------------------------------------------------------------------
// K1: QKV projection. M=2048, N=3072, K=1024. BM=BN=128, BK=16, double-buffered.
// ---------------------------------------------------------------------------
__global__ void __launch_bounds__(256) qkv_kernel(const float* __restrict__ hidden,
                                                  const float* __restrict__ W,
                                                  const float* __restrict__ qb,
                                                  const float* __restrict__ vb) {
    __shared__ float As[2][16 * 132];
    __shared__ float Bs[2][16 * 132];
    const int t = threadIdx.x, lane = t & 31, wid = t >> 5;
    const int wm0 = (wid >> 1) * 32, wn0 = (wid & 1) * 64;
    const int m0 = blockIdx.y * 128, n0 = blockIdx.x * 128;
    const int r0 = t >> 2, g = t & 3;

    float acc[2][8][4];
#pragma unroll
    for (int mt = 0; mt < 2; mt++)
#pragma unroll
        for (int nt = 0; nt < 8; nt++)
#pragma unroll
            for (int e = 0; e < 4; e++) acc[mt][nt][e] = 0.0f;

    float4 ra[2], rb[2];
    auto ldg = [&](int kt) {
        ra[0] = *(const float4*)&hidden[(size_t)(m0 + r0) * HDIM + kt + g * 4];
        ra[1] = *(const float4*)&hidden[(size_t)(m0 + r0 + 64) * HDIM + kt + g * 4];
        rb[0] = *(const float4*)&W[(size_t)(n0 + r0) * HDIM + kt + g * 4];
        rb[1] = *(const float4*)&W[(size_t)(n0 + r0 + 64) * HDIM + kt + g * 4];
    };
    auto sts = [&](int buf) {
        const float* pa = (const float*)ra;
        const float* pb = (const float*)rb;
#pragma unroll
        for (int half = 0; half < 2; half++) {
            int r = r0 + half * 64;
#pragma unroll
            for (int e = 0; e < 4; e++) {
                As[buf][(g * 4 + e) * 132 + r] = __uint_as_float(f2tf(pa[half * 4 + e]));
                Bs[buf][(g * 4 + e) * 132 + r] = __uint_as_float(f2tf(pb[half * 4 + e]));
            }
        }
    };

    ldg(0); sts(0);
    const int nt_tiles = HDIM / 16;
    for (int kt = 0; kt < nt_tiles; kt++) {
        __syncthreads();
        if (kt + 1 < nt_tiles) ldg((kt + 1) * 16);
        mma_bk16<2, 8>(As[kt & 1], 132, Bs[kt & 1], 132, wm0, wn0, lane, acc);
        if (kt + 1 < nt_tiles) sts((kt + 1) & 1);
    }

    const int kq = lane & 3, rq = lane >> 2;
#pragma unroll
    for (int mt = 0; mt < 2; mt++)
#pragma unroll
        for (int nt = 0; nt < 8; nt++)
#pragma unroll
            for (int h2 = 0; h2 < 2; h2++) {
                int m  = m0 + wm0 + mt * 16 + rq + h2 * 8;
                int cg = n0 + wn0 + nt * 8 + kq * 2;
                int head = cg / 192;
                int jj = cg - head * 192;
                float v0 = acc[mt][nt][h2 * 2], v1 = acc[mt][nt][h2 * 2 + 1];
                if (jj < 64) {
                    v0 = (v0 + qb[head * 64 + jj]) * INV_SCALE;
                    v1 = (v1 + qb[head * 64 + jj + 1]) * INV_SCALE;
                    *(float2*)&g_Q[(size_t)(head * NSEQ + m) * DH + jj] = make_float2(v0, v1);
                } else if (jj < 128) {
                    *(float2*)&g_K[(size_t)(head * NSEQ + m) * DH + jj - 64] = make_float2(v0, v1);
                } else {
                    v0 += vb[head * 64 + jj - 128];
                    v1 += vb[head * 64 + jj - 127];
                    *(float2*)&g_V[(size_t)(head * NSEQ + m) * DH + jj - 128] = make_float2(v0, v1);
                }
            }
}

// ---------------------------------------------------------------------------
// K2: position projections. z=0: PosK, z=1: PosQ. M=N=K=1024.
// ---------------------------------------------------------------------------
__global__ void __launch_bounds__(256) pos_kernel(const float* __restrict__ rel,
                                                  const float* __restrict__ Wk,
                                                  const float* __restrict__ Wq,
                                                  const float* __restrict__ bias) {
    __shared__ float As[2][16 * 132];
    __shared__ float Bs[2][16 * 132];
    const int which = blockIdx.z;
    const float* W = which == 0 ? Wk : Wq;
    const int t = threadIdx.x, lane = t & 31, wid = t >> 5;
    const int wm0 = (wid >> 1) * 32, wn0 = (wid & 1) * 64;
    const int m0 = blockIdx.y * 128, n0 = blockIdx.x * 128;
    const int r0 = t >> 2, g = t & 3;

    float acc[2][8][4];
#pragma unroll
    for (int mt = 0; mt < 2; mt++)
#pragma unroll
        for (int nt = 0; nt < 8; nt++)
#pragma unroll
            for (int e = 0; e < 4; e++) acc[mt][nt][e] = 0.0f;

    float4 ra[2], rb[2];
    auto ldg = [&](int kt) {
        ra[0] = *(const float4*)&rel[(size_t)(m0 + r0) * HDIM + kt + g * 4];
        ra[1] = *(const float4*)&rel[(size_t)(m0 + r0 + 64) * HDIM + kt + g * 4];
        rb[0] = *(const float4*)&W[(size_t)(n0 + r0) * HDIM + kt + g * 4];
        rb[1] = *(const float4*)&W[(size_t)(n0 + r0 + 64) * HDIM + kt + g * 4];
    };
    auto sts = [&](int buf) {
        const float* pa = (const float*)ra;
        const float* pb = (const float*)rb;
#pragma unroll
        for (int half = 0; half < 2; half++) {
            int r = r0 + half * 64;
#pragma unroll
            for (int e = 0; e < 4; e++) {
                As[buf][(g * 4 + e) * 132 + r] = __uint_as_float(f2tf(pa[half * 4 + e]));
                Bs[buf][(g * 4 + e) * 132 + r] = __uint_as_float(f2tf(pb[half * 4 + e]));
            }
        }
    };

    ldg(0); sts(0);
    const int nt_tiles = HDIM / 16;
    for (int kt = 0; kt < nt_tiles; kt++) {
        __syncthreads();
        if (kt + 1 < nt_tiles) ldg((kt + 1) * 16);
        mma_bk16<2, 8>(As[kt & 1], 132, Bs[kt & 1], 132, wm0, wn0, lane, acc);
        if (kt + 1 < nt_tiles) sts((kt + 1) & 1);
    }

    const int kq = lane & 3, rq = lane >> 2;
#pragma unroll
    for (int mt = 0; mt < 2; mt++)
#pragma unroll
        for (int nt = 0; nt < 8; nt++)
#pragma unroll
            for (int h2 = 0; h2 < 2; h2++) {
                int s  = m0 + wm0 + mt * 16 + rq + h2 * 8;
                int cc = n0 + wn0 + nt * 8 + kq * 2;
                int head = cc >> 6, d = cc & 63;
                float v0 = acc[mt][nt][h2 * 2], v1 = acc[mt][nt][h2 * 2 + 1];
                if (which == 0) {
                    *(float2*)&g_PosK[(size_t)(head * S2 + s) * DH + d] = make_float2(v0, v1);
                } else {
                    v0 = (v0 + bias[cc]) * INV_SCALE;
                    v1 = (v1 + bias[cc + 1]) * INV_SCALE;
                    *(float2*)&g_PosQ[(size_t)(head * S2 + s) * DH + d] = make_float2(v0, v1);
                }
            }
}

// ---------------------------------------------------------------------------
// Shared fill for K=64 tiles: [128 rows x 64 k] -> T[k][m] (pad 132), tf32.
// ---------------------------------------------------------------------------
__device__ __forceinline__ void fill_k64(const float* __restrict__ src, int row0,
                                         float* __restrict__ Ts, int t) {
#pragma unroll
    for (int i = 0; i < 8; i++) {
        int lin4 = i * 256 + t;           // 2048 float4s
        int r = lin4 >> 4, g = lin4 & 15;
        float4 v = *(const float4*)&src[(size_t)(row0 + r) * DH + g * 4];
        Ts[(g * 4 + 0) * 132 + r] = __uint_as_float(f2tf(v.x));
        Ts[(g * 4 + 1) * 132 + r] = __uint_as_float(f2tf(v.y));
        Ts[(g * 4 + 2) * 132 + r] = __uint_as_float(f2tf(v.z));
        Ts[(g * 4 + 3) * 132 + r] = __uint_as_float(f2tf(v.w));
    }
}

// ---------------------------------------------------------------------------
// K3: raw relative scores. z = h + 16*which. K=64 single-shot.
// ---------------------------------------------------------------------------
__global__ void __launch_bounds__(256) relsc_kernel() {
    extern __shared__ float sm[];
    float* As = sm;
    float* Bs = sm + 64 * 132;
    const int z = blockIdx.z;
    const int h = z & 15, which = z >> 4;
    const int m0 = blockIdx.y * 128, n0 = blockIdx.x * 128;
    const float* A = (which == 0 ? g_Q : g_K) + (size_t)h * NSEQ * DH;
    const float* B = (which == 0 ? g_PosK : g_PosQ) + (size_t)h * S2 * DH;
    float* O = (which == 0 ? g_c2p : g_p2c);

    const int t = threadIdx.x, lane = t & 31, wid = t >> 5;
    const int wm0 = (wid >> 1) * 32, wn0 = (wid & 1) * 64;

    fill_k64(A, m0, As, t);
    fill_k64(B, n0, Bs, t);
    __syncthreads();

    float acc[2][8][4];
#pragma unroll
    for (int mt = 0; mt < 2; mt++)
#pragma unroll
        for (int nt = 0; nt < 8; nt++)
#pragma unroll
            for (int e = 0; e < 4; e++) acc[mt][nt][e] = 0.0f;

#pragma unroll
    for (int s16 = 0; s16 < 4; s16++)
        mma_bk16<2, 8>(As + s16 * 16 * 132, 132, Bs + s16 * 16 * 132, 132,
                       wm0, wn0, lane, acc);

    const int kq = lane & 3, rq = lane >> 2;
#pragma unroll
    for (int mt = 0; mt < 2; mt++)
#pragma unroll
        for (int nt = 0; nt < 8; nt++)
#pragma unroll
            for (int h2 = 0; h2 < 2; h2++) {
                int m = m0 + wm0 + mt * 16 + rq + h2 * 8;
                int n = n0 + wn0 + nt * 8 + kq * 2;
                *(float2*)&O[((size_t)(h * NSEQ + m)) * S2 + n] =
                    make_float2(acc[mt][nt][h2 * 2], acc[mt][nt][h2 * 2 + 1]);
            }
}

// ---------------------------------------------------------------------------
// K4: scores = QK^T + c2p + p2c + mask, with per-(row, 64-col halftile) stats.
// smem reuse: the 2x(64x132) MMA tiles are reused as ONE 128x132 bias tile G
// (c2p fill, then += p2c transposed). Total smem 67.5 KB -> 2 CTAs/SM.
// ---------------------------------------------------------------------------
__global__ void __launch_bounds__(256, 2) scores_kernel(const int* __restrict__ mask) {
    extern __shared__ float sm[];
    float* As = sm;              // 64 x 132
    float* Bs = sm + 64 * 132;   // 64 x 132
    float* G  = sm;              // reused as 128 x 132 after MMA

    const int h  = blockIdx.z;
    const int m0 = blockIdx.y * 128, n0 = blockIdx.x * 128;
    const int t = threadIdx.x, lane = t & 31, wid = t >> 5;
    const int wm0 = (wid >> 1) * 32, wn0 = (wid & 1) * 64;

    fill_k64(g_Q + (size_t)h * NSEQ * DH, m0, As, t);
    fill_k64(g_K + (size_t)h * NSEQ * DH, n0, Bs, t);
    __syncthreads();

    float acc[2][8][4];
#pragma unroll
    for (int mt = 0; mt < 2; mt++)
#pragma unroll
        for (int nt = 0; nt < 8; nt++)
#pragma unroll
            for (int e = 0; e < 4; e++) acc[mt][nt][e] = 0.0f;

#pragma unroll
    for (int s16 = 0; s16 < 4; s16++)
        mma_bk16<2, 8>(As + s16 * 16 * 132, 132, Bs + s16 * 16 * 132, 132,
                       wm0, wn0, lane, acc);
    __syncthreads();   // done with As/Bs -> reuse as G

    const float* C2 = g_c2p + (size_t)h * NSEQ * S2;
    const float* P2 = g_p2c + (size_t)h * NSEQ * S2;
    // G = c2p tile (coalesced along k-local)
#pragma unroll
    for (int i = 0; i < 64; i++) {
        int lin = i * 256 + t;
        int r = lin >> 7, j = lin & 127;
        int q = m0 + r, kc = n0 + j;
        int idx = q - kc + SPAN;
        idx = idx < 0 ? 0 : (idx > S2 - 1 ? S2 - 1 : idx);
        G[r * 132 + j] = C2[(size_t)q * S2 + idx];
    }
    __syncthreads();
    // G += p2c (global reads coalesced along q, smem writes transposed)
#pragma unroll
    for (int i = 0; i < 64; i++) {
        int lin = i * 256 + t;
        int jr = lin >> 7, qi = lin & 127;
        int kc = n0 + jr, q = m0 + qi;
        int idx = q - kc + SPAN;
        idx = idx < 0 ? 0 : (idx > S2 - 1 ? S2 - 1 : idx);
        G[qi * 132 + jr] += P2[(size_t)kc * S2 + idx];
    }
    __syncthreads();

    // epilogue: finalize, store raw scores, emit per-(row, halftile) stats
    const int kq = lane & 3, rq = lane >> 2;
    const int ht = blockIdx.x * 2 + (wn0 >> 6);
#pragma unroll
    for (int mt = 0; mt < 2; mt++)
#pragma unroll
        for (int h2 = 0; h2 < 2; h2++) {
            const int rm = wm0 + mt * 16 + rq + h2 * 8;
            const int q = m0 + rm;
            float vals[16];
            float rmax = -INFINITY;
#pragma unroll
            for (int nt = 0; nt < 8; nt++) {
                int rn = wn0 + nt * 8 + kq * 2;
                int kc = n0 + rn;
                float2 gb = *(const float2*)&G[rm * 132 + rn];
                int2 mk = *(const int2*)&mask[(size_t)q * NSEQ + kc];
                float v0 = acc[mt][nt][h2 * 2]     + gb.x;
                float v1 = acc[mt][nt][h2 * 2 + 1] + gb.y;
                if (mk.x == 0) v0 = -1e30f;
                if (mk.y == 0) v1 = -1e30f;
                *(float2*)&g_sc[((size_t)(h * NSEQ + q)) * NSEQ + kc] = make_float2(v0, v1);
                vals[nt * 2] = v0; vals[nt * 2 + 1] = v1;
                rmax = fmaxf(rmax, fmaxf(v0, v1));
            }
            rmax = fmaxf(rmax, __shfl_xor_sync(0xffffffffu, rmax, 1));
            rmax = fmaxf(rmax, __shfl_xor_sync(0xffffffffu, rmax, 2));
            float rsum = 0.0f;
#pragma unroll
            for (int e = 0; e < 16; e++) rsum += __expf(vals[e] - rmax);
            rsum += __shfl_xor_sync(0xffffffffu, rsum, 1);
            rsum += __shfl_xor_sync(0xffffffffu, rsum, 2);
            if (kq == 0) {
                g_statM[((size_t)(h * NSEQ + q)) * 32 + ht] = rmax;
                g_statL[((size_t)(h * NSEQ + q)) * 32 + ht] = rsum;
            }
        }
}

// ---------------------------------------------------------------------------
// K5: combine per-halftile stats into row max / inv-sum
// ---------------------------------------------------------------------------
__global__ void __launch_bounds__(256) combine_kernel() {
    const int row = blockIdx.x * 256 + threadIdx.x;   // h*NSEQ + q
    const size_t b = (size_t)row * 32;
    float m = -INFINITY;
#pragma unroll
    for (int i = 0; i < 32; i++) m = fmaxf(m, g_statM[b + i]);
    float l = 0.0f;
#pragma unroll
    for (int i = 0; i < 32; i++) l += g_statL[b + i] * __expf(g_statM[b + i] - m);
    g_rowM[row]   = m;
    g_rowInv[row] = 1.0f / l;
}

// ---------------------------------------------------------------------------
// K6: split-K PV. grid (m-tiles=16, heads=16, kz=4). BM=128, BN=64, BK=16.
// exp/normalize fused into A fill. Partials to g_pvp.
// ---------------------------------------------------------------------------
__global__ void __launch_bounds__(256) pv_kernel() {
    __shared__ float As[2][16 * 132];
    __shared__ float Bs[2][16 * 68];
    __shared__ float rowm[128], rowi[128];

    const int mt0 = blockIdx.x, h = blockIdx.y, kz = blockIdx.z;
    const int m0 = mt0 * 128;
    const int kbase = kz * (NSEQ / 4);
    const int t = threadIdx.x, lane = t & 31, wid = t >> 5;
    const int wm0 = wid * 16;   // 8 warps x 16 rows
    const float* Ag = g_sc + (size_t)h * NSEQ * NSEQ;
    const float* Vg = g_V + (size_t)h * NSEQ * DH;

    if (t < 128) {
        rowm[t] = g_rowM[h * NSEQ + m0 + t];
        rowi[t] = g_rowInv[h * NSEQ + m0 + t];
    }
    __syncthreads();

    float acc[1][8][4];
#pragma unroll
    for (int nt = 0; nt < 8; nt++)
#pragma unroll
        for (int e = 0; e < 4; e++) acc[0][nt][e] = 0.0f;

    const int ra0 = t >> 2, ga = t & 3;
    const int rb0 = t >> 4, gb = t & 15;
    float4 pa[2], pb;
    auto ldg = [&](int kt) {
        pa[0] = *(const float4*)&Ag[(size_t)(m0 + ra0) * NSEQ + kbase + kt + ga * 4];
        pa[1] = *(const float4*)&Ag[(size_t)(m0 + ra0 + 64) * NSEQ + kbase + kt + ga * 4];
        pb    = *(const float4*)&Vg[(size_t)(kbase + kt + rb0) * DH + gb * 4];
    };
    auto sts = [&](int buf) {
#pragma unroll
        for (int half = 0; half < 2; half++) {
            int r = ra0 + half * 64;
            float m = rowm[r], iv = rowi[r];
            const float* p = (const float*)&pa[half];
#pragma unroll
            for (int e = 0; e < 4; e++) {
                float prob = __expf(p[e] - m) * iv;
                As[buf][(ga * 4 + e) * 132 + r] = __uint_as_float(f2tf(prob));
            }
        }
        const float* q = (const float*)&pb;
#pragma unroll
        for (int e = 0; e < 4; e++)
            Bs[buf][rb0 * 68 + gb * 4 + e] = __uint_as_float(f2tf(q[e]));
    };

    ldg(0); sts(0);
    const int ntile = (NSEQ / 4) / 16;   // 32
    for (int kt = 0; kt < ntile; kt++) {
        __syncthreads();
        if (kt + 1 < ntile) ldg((kt + 1) * 16);
        mma_bk16<1, 8>(As[kt & 1], 132, Bs[kt & 1], 68, wm0, 0, lane, acc);
        if (kt + 1 < ntile) sts((kt + 1) & 1);
    }

    const int kq = lane & 3, rq = lane >> 2;
    float* P = g_pvp + ((size_t)(kz * NHEAD + h) * NSEQ) * DH;
#pragma unroll
    for (int nt = 0; nt < 8; nt++)
#pragma unroll
        for (int h2 = 0; h2 < 2; h2++) {
            int m = m0 + wm0 + rq + h2 * 8;
            int n = nt * 8 + kq * 2;
            *(float2*)&P[(size_t)m * DH + n] =
                make_float2(acc[0][nt][h2 * 2], acc[0][nt][h2 * 2 + 1]);
        }
}

// ---------------------------------------------------------------------------
// K7: reduce split-K partials into output [m][h*64+d]
// ---------------------------------------------------------------------------
__global__ void __launch_bounds__(256) reduce_kernel(float* __restrict__ out) {
    int gid = blockIdx.x * 256 + threadIdx.x;   // over 2048*1024
    int m = gid >> 10;
    int c = gid & 1023;
    int h = c >> 6, d = c & 63;
    float s = 0.0f;
#pragma unroll
    for (int z = 0; z < 4; z++)
        s += g_pvp[((size_t)(z * NHEAD + h) * NSEQ + m) * DH + d];
    out[gid] = s;
}

// ---------------------------------------------------------------------------
extern "C" void kernel_launch(void* const* d_in, const int* in_sizes, int n_in,
                              void* d_out, int out_size) {
    const float* hidden   = (const float*)d_in[0];
    const int*   mask     = (const int*)  d_in[1];
    const float* rel_emb  = (const float*)d_in[3];
    const float* in_proj  = (const float*)d_in[4];
    const float* q_bias   = (const float*)d_in[5];
    const float* v_bias   = (const float*)d_in[6];
    const float* pos_w    = (const float*)d_in[7];
    const float* pos_q_w  = (const float*)d_in[8];
    const float* pos_q_b  = (const float*)d_in[9];
    float* out = (float*)d_out;

    const int k64_smem = 2 * 64 * 132 * 4;   // 67584 bytes
    cudaFuncSetAttribute(relsc_kernel, cudaFuncAttributeMaxDynamicSharedMemorySize,
                         k64_smem);
    cudaFuncSetAttribute(scores_kernel, cudaFuncAttributeMaxDynamicSharedMemorySize,
                         k64_smem);

    // K1: QKV projection
    qkv_kernel<<<dim3(3072 / 128, 2048 / 128), 256>>>(hidden, in_proj, q_bias, v_bias);

    // K2: position projections
    pos_kernel<<<dim3(HDIM / 128, S2 / 128, 2), 256>>>(rel_emb, pos_w, pos_q_w, pos_q_b);

    // K3: c2p_raw / p2c_raw
    relsc_kernel<<<dim3(S2 / 128, NSEQ / 128, NHEAD * 2), 256, k64_smem>>>();

    // K4: scores (+ per-tile stats)
    scores_kernel<<<dim3(NSEQ / 128, NSEQ / 128, NHEAD), 256, k64_smem>>>(mask);

    // K5: combine stats
    combine_kernel<<<(NHEAD * NSEQ) / 256, 256>>>();

    // K6: split-K PV
    pv_kernel<<<dim3(NSEQ / 128, NHEAD, 4), 256>>>();

    // K7: reduce
    reduce_kernel<<<(NSEQ * HDIM) / 256, 256>>>(out);
}